// round 2
// baseline (speedup 1.0000x reference)
#include <cuda_runtime.h>

// Problem constants (CoordinationMemory): N=4096, L_V=64, H=512, D=256
constexpr int NB   = 4096;   // batch
constexpr int LV   = 64;     // memory slots
constexpr int HD   = 512;    // hidden
constexpr int DD   = 256;    // repr dim
constexpr int K1   = 3 * DD; // 768 (x @ W_in)
constexpr int KTOT = K1 + HD; // 1280 total reduction

// Tiling
#define BM 128
#define BN 128
#define BK 8
#define TM 8
#define TN 8
// 256 threads per block; (BM/TM)*(BN/TN) = 16*16 = 256

__global__ __launch_bounds__(256, 1)
void coord_mem_gemm(const float* __restrict__ memory,
                    const int* __restrict__ veh_idx,   // int32 (jax x64 disabled)
                    const float* __restrict__ veh_repr,
                    const float* __restrict__ cust_repr,
                    const float* __restrict__ edge_emb,
                    const float* __restrict__ W_in,
                    const float* __restrict__ b_in,
                    const float* __restrict__ W_h,
                    const float* __restrict__ b_h,
                    float* __restrict__ out)
{
    __shared__ float As[BK][BM];   // A^T tile: As[k][m]
    __shared__ float Bs[BK][BN];
    __shared__ int   idx_s[BM];

    const int block_m = blockIdx.y * BM;
    const int block_n = blockIdx.x * BN;
    const int tid = threadIdx.x;

    // thread micro-tile position
    const int tm = (tid / (BN / TN)) * TM;   // 0..120 step 8
    const int tn = (tid % (BN / TN)) * TN;   // 0..120 step 8

    // defensive mask: LV=64 is pow2, in-range values unaffected
    if (tid < BM) idx_s[tid] = veh_idx[block_m + tid] & (LV - 1);
    __syncthreads();

    float acc[TM][TN];
    #pragma unroll
    for (int i = 0; i < TM; i++)
        #pragma unroll
        for (int j = 0; j < TN; j++) acc[i][j] = 0.0f;

    for (int k0 = 0; k0 < KTOT; k0 += BK) {
        // --- load A tile: BM x BK = 1024 elems, 4 per thread ---
        #pragma unroll
        for (int i = 0; i < 4; i++) {
            int e  = tid + i * 256;      // 0..1023
            int m  = e >> 3;             // e / BK
            int k  = e & 7;              // e % BK
            int gk = k0 + k;
            int gm = block_m + m;
            float v;
            if (gk < DD) {
                v = veh_repr[gm * DD + gk];
            } else if (gk < 2 * DD) {
                v = cust_repr[gm * DD + (gk - DD)];
            } else if (gk < K1) {
                v = edge_emb[gm * DD + (gk - 2 * DD)];
            } else {
                v = memory[((long)gm * LV + idx_s[m]) * HD + (gk - K1)];
            }
            As[k][m] = v;
        }
        // --- load B tile: BK x BN = 1024 elems, 4 per thread ---
        #pragma unroll
        for (int i = 0; i < 4; i++) {
            int e  = tid + i * 256;
            int k  = e >> 7;             // e / BN
            int n  = e & 127;            // e % BN
            int gk = k0 + k;
            float v = (gk < K1) ? W_in[(long)gk * HD + block_n + n]
                                : W_h[(long)(gk - K1) * HD + block_n + n];
            Bs[k][n] = v;
        }
        __syncthreads();

        #pragma unroll
        for (int k = 0; k < BK; k++) {
            float a[TM], b[TN];
            #pragma unroll
            for (int i = 0; i < TM; i++) a[i] = As[k][tm + i];
            #pragma unroll
            for (int j = 0; j < TN; j++) b[j] = Bs[k][tn + j];
            #pragma unroll
            for (int i = 0; i < TM; i++)
                #pragma unroll
                for (int j = 0; j < TN; j++)
                    acc[i][j] += a[i] * b[j];
        }
        __syncthreads();
    }

    // --- epilogue: bias + tanh, scatter into out[n, idx[n], :] ---
    #pragma unroll
    for (int i = 0; i < TM; i++) {
        int gm = block_m + tm + i;
        long base = ((long)gm * LV + idx_s[tm + i]) * HD + block_n + tn;
        #pragma unroll
        for (int j = 0; j < TN; j++) {
            int n = block_n + tn + j;
            out[base + j] = tanhf(acc[i][j] + b_in[n] + b_h[n]);
        }
    }
}

extern "C" void kernel_launch(void* const* d_in, const int* in_sizes, int n_in,
                              void* d_out, int out_size)
{
    const float* memory    = (const float*)d_in[0];
    const int*   veh_idx   = (const int*)d_in[1];
    const float* veh_repr  = (const float*)d_in[2];
    const float* cust_repr = (const float*)d_in[3];
    const float* edge_emb  = (const float*)d_in[4];
    const float* W_in      = (const float*)d_in[5];
    const float* b_in      = (const float*)d_in[6];
    const float* W_h       = (const float*)d_in[7];
    const float* b_h       = (const float*)d_in[8];
    float*       out       = (float*)d_out;

    // 1) passthrough copy: out = memory  (512 MB, D2D)
    cudaMemcpyAsync(out, memory, (size_t)NB * LV * HD * sizeof(float),
                    cudaMemcpyDeviceToDevice, 0);

    // 2) fused GEMM + gather + bias + tanh + scatter (same stream -> ordered)
    dim3 grid(HD / BN, NB / BM);   // (4, 32) = 128 blocks
    coord_mem_gemm<<<grid, 256>>>(memory, veh_idx, veh_repr, cust_repr,
                                  edge_emb, W_in, b_in, W_h, b_h, out);
}

// round 3
// speedup vs baseline: 2.1691x; 2.1691x over previous
#include <cuda_runtime.h>

// Problem constants (CoordinationMemory): N=4096, L_V=64, H=512, D=256
constexpr int NB   = 4096;
constexpr int LV   = 64;
constexpr int HD   = 512;
constexpr int DD   = 256;
constexpr int K1   = 3 * DD;   // 768
constexpr int KTOT = K1 + HD;  // 1280

// GEMM tiling
constexpr int BM = 128, BN = 128, BK = 8;
constexpr int TM = 8,   TN = 8;
constexpr int GEMM_CTAS = (NB / BM) * (HD / BN);  // 32*4 = 128

// Fused grid: 2 CTAs/SM on 152 SMs
constexpr int TOTAL_CTAS = 304;

// Copy work: rows of 512 floats (2KB). 262144 rows total.
constexpr int ROWS_TOTAL     = NB * LV;          // 262144
constexpr int ROWS_PER_GRAB  = 32;               // grabs always within one n
constexpr int NUM_GRABS      = ROWS_TOTAL / ROWS_PER_GRAB;  // 8192

__device__ int g_copy_ctr;

__global__ void reset_kernel() { g_copy_ctr = 0; }

// --------------------------------------------------------------------------
// Copy role: work-stealing passthrough out[r,:] = memory[r,:] for all rows
// except the row each batch's GEMM scatter will write (l == veh_idx[n]).
// Coalesced float4: lane j touches float4 index (lane + 32*j) within the row.
// --------------------------------------------------------------------------
__device__ __forceinline__ void copy_role(const float4* __restrict__ src,
                                          float4* __restrict__ dst,
                                          const int* __restrict__ veh_idx,
                                          int lane)
{
    for (;;) {
        int c;
        if (lane == 0) c = atomicAdd(&g_copy_ctr, 1);
        c = __shfl_sync(0xffffffffu, c, 0);
        if (c >= NUM_GRABS) return;

        int r0     = c * ROWS_PER_GRAB;           // multiple of 32
        int n      = r0 >> 6;                     // constant for whole grab
        int skip_l = veh_idx[n] & (LV - 1);
        int l0     = r0 & 63;                     // 0 or 32

        #pragma unroll 4
        for (int i = 0; i < ROWS_PER_GRAB; i++) {
            if (l0 + i == skip_l) continue;       // GEMM writes this row
            size_t base = (size_t)(r0 + i) * (HD / 4);
            const float4* s = src + base;
            float4*       d = dst + base;
            d[lane]      = s[lane];
            d[lane + 32] = s[lane + 32];
            d[lane + 64] = s[lane + 64];
            d[lane + 96] = s[lane + 96];
        }
    }
}

// --------------------------------------------------------------------------
// Fused kernel: bids [0, GEMM_CTAS) compute one output tile of
//   tanh(X@W_in + b_in + cur_h@W_h + b_h) scattered into out[n, idx[n], :],
// then (and all other bids from the start) join the copy work pool.
// --------------------------------------------------------------------------
__global__ __launch_bounds__(256, 2)
void fused_kernel(const float* __restrict__ memory,
                  const int*   __restrict__ veh_idx,
                  const float* __restrict__ veh_repr,
                  const float* __restrict__ cust_repr,
                  const float* __restrict__ edge_emb,
                  const float* __restrict__ W_in,
                  const float* __restrict__ b_in,
                  const float* __restrict__ W_h,
                  const float* __restrict__ b_h,
                  float* __restrict__ out)
{
    __shared__ float As[BK][BM];
    __shared__ float Bs[BK][BN];
    __shared__ int   idx_s[BM];

    const int tid  = threadIdx.x;
    const int bid  = blockIdx.x;
    const int lane = tid & 31;

    if (bid < GEMM_CTAS) {
        const int block_m = (bid >> 2) * BM;   // 32 m-tiles
        const int block_n = (bid & 3) * BN;    // 4 n-tiles

        const int tm = (tid / (BN / TN)) * TM;
        const int tn = (tid % (BN / TN)) * TN;

        if (tid < BM) idx_s[tid] = veh_idx[block_m + tid] & (LV - 1);
        __syncthreads();

        float acc[TM][TN];
        #pragma unroll
        for (int i = 0; i < TM; i++)
            #pragma unroll
            for (int j = 0; j < TN; j++) acc[i][j] = 0.0f;

        // A-load mapping: thread -> (m, k4): one float4 along k
        const int am = tid >> 1;
        const int ak = (tid & 1) * 4;
        const int agm = block_m + am;
        // B-load mapping: thread -> (kb, n4): one float4 along n
        const int bk = tid >> 5;
        const int bn = (tid & 31) * 4;

        for (int k0 = 0; k0 < KTOT; k0 += BK) {
            // ---- A tile (BM x BK), one float4 per thread ----
            // region is uniform per k0 (boundaries are multiples of BK)
            float4 av;
            if (k0 < DD) {
                av = *(const float4*)&veh_repr[agm * DD + k0 + ak];
            } else if (k0 < 2 * DD) {
                av = *(const float4*)&cust_repr[agm * DD + (k0 - DD) + ak];
            } else if (k0 < K1) {
                av = *(const float4*)&edge_emb[agm * DD + (k0 - 2 * DD) + ak];
            } else {
                av = *(const float4*)&memory[((size_t)agm * LV + idx_s[am]) * HD
                                             + (k0 - K1) + ak];
            }
            As[ak + 0][am] = av.x;
            As[ak + 1][am] = av.y;
            As[ak + 2][am] = av.z;
            As[ak + 3][am] = av.w;

            // ---- B tile (BK x BN), one float4 per thread ----
            {
                int gk = k0 + bk;
                const float* brow = (gk < K1) ? &W_in[(size_t)gk * HD]
                                              : &W_h[(size_t)(gk - K1) * HD];
                *(float4*)&Bs[bk][bn] = *(const float4*)&brow[block_n + bn];
            }
            __syncthreads();

            #pragma unroll
            for (int k = 0; k < BK; k++) {
                float a[TM], b[TN];
                #pragma unroll
                for (int i = 0; i < TM; i++) a[i] = As[k][tm + i];
                #pragma unroll
                for (int j = 0; j < TN; j++) b[j] = Bs[k][tn + j];
                #pragma unroll
                for (int i = 0; i < TM; i++)
                    #pragma unroll
                    for (int j = 0; j < TN; j++)
                        acc[i][j] += a[i] * b[j];
            }
            __syncthreads();
        }

        // ---- epilogue: bias + tanh, scatter to out[n, idx[n], :] ----
        float bias[TN];
        #pragma unroll
        for (int j = 0; j < TN; j++) {
            int n = block_n + tn + j;
            bias[j] = b_in[n] + b_h[n];
        }
        #pragma unroll
        for (int i = 0; i < TM; i++) {
            int gm = block_m + tm + i;
            float* dst = &out[((size_t)gm * LV + idx_s[tm + i]) * HD
                              + block_n + tn];
            float4 o0, o1;
            o0.x = tanhf(acc[i][0] + bias[0]);
            o0.y = tanhf(acc[i][1] + bias[1]);
            o0.z = tanhf(acc[i][2] + bias[2]);
            o0.w = tanhf(acc[i][3] + bias[3]);
            o1.x = tanhf(acc[i][4] + bias[4]);
            o1.y = tanhf(acc[i][5] + bias[5]);
            o1.z = tanhf(acc[i][6] + bias[6]);
            o1.w = tanhf(acc[i][7] + bias[7]);
            *(float4*)&dst[0] = o0;
            *(float4*)&dst[4] = o1;
        }
    }

    // Everyone ends in the copy pool (copy-only CTAs start here immediately).
    copy_role((const float4*)memory, (float4*)out, veh_idx, lane);
}

extern "C" void kernel_launch(void* const* d_in, const int* in_sizes, int n_in,
                              void* d_out, int out_size)
{
    const float* memory    = (const float*)d_in[0];
    const int*   veh_idx   = (const int*)d_in[1];
    const float* veh_repr  = (const float*)d_in[2];
    const float* cust_repr = (const float*)d_in[3];
    const float* edge_emb  = (const float*)d_in[4];
    const float* W_in      = (const float*)d_in[5];
    const float* b_in      = (const float*)d_in[6];
    const float* W_h       = (const float*)d_in[7];
    const float* b_h       = (const float*)d_in[8];
    float*       out       = (float*)d_out;

    reset_kernel<<<1, 1>>>();
    fused_kernel<<<TOTAL_CTAS, 256>>>(memory, veh_idx, veh_repr, cust_repr,
                                      edge_emb, W_in, b_in, W_h, b_h, out);
}

// round 4
// speedup vs baseline: 2.5814x; 1.1901x over previous
#include <cuda_runtime.h>
#include <cstdint>

// Problem constants: N=4096, L_V=64, H=512, D=256
constexpr int NB   = 4096;
constexpr int LV   = 64;
constexpr int HD   = 512;
constexpr int DD   = 256;
constexpr int K1   = 3 * DD;   // 768
constexpr int KTOT = K1 + HD;  // 1280

// GEMM tiling
constexpr int BM = 128, BN = 128, BK = 16;
constexpr int TM = 8,   TN = 8;
constexpr int NIT  = KTOT / BK;  // 80
constexpr int ASTR = 20;         // padded floats per A-row (16 + 4), keeps 16B align
constexpr int GEMM_CTAS  = (NB / BM) * (HD / BN);  // 128
constexpr int TOTAL_CTAS = 304;                    // 2 per SM on 152 SMs

// Copy pool
constexpr int ROWS_TOTAL = NB * LV;                // 262144 rows of 512 floats
constexpr int NUM_GRABS  = ROWS_TOTAL / 32;        // 8192, 32 rows per grab

__device__ int g_copy_ctr;

__global__ void reset_kernel() { g_copy_ctr = 0; }

// ---------------- PTX helpers ----------------
__device__ __forceinline__ uint32_t s2u(const void* p) {
    uint32_t a;
    asm("{ .reg .u64 t; cvta.to.shared.u64 t, %1; cvt.u32.u64 %0, t; }"
        : "=r"(a) : "l"(p));
    return a;
}
__device__ __forceinline__ void cp16(uint32_t dst, const void* src) {
    asm volatile("cp.async.cg.shared.global [%0], [%1], 16;" :: "r"(dst), "l"(src));
}
__device__ __forceinline__ void cp_commit() {
    asm volatile("cp.async.commit_group;");
}
template <int N>
__device__ __forceinline__ void cp_wait() {
    asm volatile("cp.async.wait_group %0;" :: "n"(N));
}

// --------------------------------------------------------------------------
// Copy role: work-stealing passthrough with deep MLP.
// Each warp grabs 32 rows; processes 4 rows at a time: 16 LDG.128 in flight,
// then 16 STG.128 (store skipped for the row the GEMM scatters).
// --------------------------------------------------------------------------
__device__ __forceinline__ void copy_role(const float4* __restrict__ src,
                                          float4* __restrict__ dst,
                                          const int* __restrict__ veh_idx,
                                          int lane)
{
    for (;;) {
        int c;
        if (lane == 0) c = atomicAdd(&g_copy_ctr, 1);
        c = __shfl_sync(0xffffffffu, c, 0);
        if (c >= NUM_GRABS) return;

        const int r0   = c * 32;            // multiple of 32 -> same n whole grab
        const int n    = r0 >> 6;
        const int skip = veh_idx[n] & (LV - 1);
        const int l0   = r0 & 63;           // 0 or 32

        for (int g = 0; g < 8; g++) {       // 8 groups of 4 rows
            float4 v[16];
            size_t base = (size_t)(r0 + g * 4) * (HD / 4) + lane;
            #pragma unroll
            for (int rr = 0; rr < 4; rr++)
                #pragma unroll
                for (int q = 0; q < 4; q++)
                    v[rr * 4 + q] = src[base + rr * 128 + q * 32];
            #pragma unroll
            for (int rr = 0; rr < 4; rr++) {
                if (l0 + g * 4 + rr == skip) continue;   // GEMM owns this row
                #pragma unroll
                for (int q = 0; q < 4; q++)
                    dst[base + rr * 128 + q * 32] = v[rr * 4 + q];
            }
        }
    }
}

// --------------------------------------------------------------------------
// Fused kernel.
//  bids [0,128): one 128x128 tile of tanh(X@W_in + cur_h@W_h + b) scattered
//  into out[n, idx[n], :], with cp.async double-buffered mainloop.
//  All CTAs end in (copy-only CTAs start in) the copy pool.
// --------------------------------------------------------------------------
__global__ __launch_bounds__(256, 2)
void fused_kernel(const float* __restrict__ memory,
                  const int*   __restrict__ veh_idx,
                  const float* __restrict__ veh_repr,
                  const float* __restrict__ cust_repr,
                  const float* __restrict__ edge_emb,
                  const float* __restrict__ W_in,
                  const float* __restrict__ b_in,
                  const float* __restrict__ W_h,
                  const float* __restrict__ b_h,
                  float* __restrict__ out)
{
    __shared__ float As2[2][BM][ASTR];   // A tiles, [m][k] with pad
    __shared__ float Bs[2][BK][BN];      // B tiles, [k][n]
    __shared__ int   idx_s[BM];

    const int tid  = threadIdx.x;
    const int bid  = blockIdx.x;
    const int lane = tid & 31;

    if (bid < GEMM_CTAS) {
        const int block_m = (bid >> 2) * BM;
        const int block_n = (bid & 3) * BN;

        if (tid < BM) idx_s[tid] = veh_idx[block_m + tid] & (LV - 1);
        __syncthreads();

        // --- A cp.async mapping: 512 16B-chunks = 128 m x 4 k-chunks; 2/thread
        const int m0  = tid >> 2;            // 0..63
        const int kc  = (tid & 3) * 4;       // k offset in floats: 0,4,8,12
        const int gm0 = block_m + m0;
        const int gm1 = gm0 + 64;
        const size_t memrow0 = ((size_t)gm0 * LV + idx_s[m0])      * HD;
        const size_t memrow1 = ((size_t)gm1 * LV + idx_s[m0 + 64]) * HD;
        const uint32_t aDst0 = s2u(&As2[0][m0][kc]);
        const uint32_t aDst1 = s2u(&As2[0][m0 + 64][kc]);

        // --- B cp.async mapping: 512 chunks = 16 k x 32 n-chunks; 2/thread
        const int kb = tid >> 5;             // 0..7 (+8 for second)
        const int nc = (tid & 31) * 4;
        const uint32_t bDst0 = s2u(&Bs[0][kb][nc]);
        const uint32_t bDst1 = s2u(&Bs[0][kb + 8][nc]);

        auto issue_tile = [&](int it, int buf) {
            const int k0 = it * BK;
            const uint32_t aoff = buf ? (uint32_t)(BM * ASTR * 4) : 0u;
            const uint32_t boff = buf ? (uint32_t)(BK * BN * 4)   : 0u;
            const float *s0, *s1;
            if (k0 < DD) {
                s0 = veh_repr + (size_t)gm0 * DD + k0 + kc;
                s1 = veh_repr + (size_t)gm1 * DD + k0 + kc;
            } else if (k0 < 2 * DD) {
                const int o = k0 - DD;
                s0 = cust_repr + (size_t)gm0 * DD + o + kc;
                s1 = cust_repr + (size_t)gm1 * DD + o + kc;
            } else if (k0 < K1) {
                const int o = k0 - 2 * DD;
                s0 = edge_emb + (size_t)gm0 * DD + o + kc;
                s1 = edge_emb + (size_t)gm1 * DD + o + kc;
            } else {
                const int o = k0 - K1;
                s0 = memory + memrow0 + o + kc;
                s1 = memory + memrow1 + o + kc;
            }
            cp16(aDst0 + aoff, s0);
            cp16(aDst1 + aoff, s1);

            const int gk0 = k0 + kb;
            const int gk1 = gk0 + 8;
            const float* w0 = (gk0 < K1) ? (W_in + (size_t)gk0 * HD)
                                         : (W_h + (size_t)(gk0 - K1) * HD);
            const float* w1 = (gk1 < K1) ? (W_in + (size_t)gk1 * HD)
                                         : (W_h + (size_t)(gk1 - K1) * HD);
            cp16(bDst0 + boff, w0 + block_n + nc);
            cp16(bDst1 + boff, w1 + block_n + nc);
            cp_commit();
        };

        const int tm = (tid >> 4) * TM;     // (tid/16)*8
        const int tn = (tid & 15) * TN;     // (tid%16)*8

        float acc[TM][TN];
        #pragma unroll
        for (int i = 0; i < TM; i++)
            #pragma unroll
            for (int j = 0; j < TN; j++) acc[i][j] = 0.0f;

        issue_tile(0, 0);

        for (int it = 0; it < NIT; it++) {
            const int buf = it & 1;
            if (it + 1 < NIT) {
                issue_tile(it + 1, buf ^ 1);
                cp_wait<1>();                // tile 'it' complete
            } else {
                cp_wait<0>();
            }
            __syncthreads();

            #pragma unroll
            for (int k2 = 0; k2 < BK / 2; k2++) {
                float2 a2[TM];
                #pragma unroll
                for (int i = 0; i < TM; i++)
                    a2[i] = *(const float2*)&As2[buf][tm + i][2 * k2];

                float b0[TN], b1[TN];
                *(float4*)&b0[0] = *(const float4*)&Bs[buf][2 * k2][tn];
                *(float4*)&b0[4] = *(const float4*)&Bs[buf][2 * k2][tn + 4];
                *(float4*)&b1[0] = *(const float4*)&Bs[buf][2 * k2 + 1][tn];
                *(float4*)&b1[4] = *(const float4*)&Bs[buf][2 * k2 + 1][tn + 4];

                #pragma unroll
                for (int i = 0; i < TM; i++) {
                    #pragma unroll
                    for (int j = 0; j < TN; j++) {
                        acc[i][j] += a2[i].x * b0[j];
                        acc[i][j] += a2[i].y * b1[j];
                    }
                }
            }
            __syncthreads();   // buffer 'buf' free for tile it+2's cp.async
        }

        // ---- epilogue: bias + tanh, scatter to out[n, idx[n], :] ----
        float bias[TN];
        #pragma unroll
        for (int j = 0; j < TN; j++) {
            const int n = block_n + tn + j;
            bias[j] = b_in[n] + b_h[n];
        }
        #pragma unroll
        for (int i = 0; i < TM; i++) {
            const int gm = block_m + tm + i;
            float* dst = &out[((size_t)gm * LV + idx_s[tm + i]) * HD
                              + block_n + tn];
            float4 o0, o1;
            o0.x = tanhf(acc[i][0] + bias[0]);
            o0.y = tanhf(acc[i][1] + bias[1]);
            o0.z = tanhf(acc[i][2] + bias[2]);
            o0.w = tanhf(acc[i][3] + bias[3]);
            o1.x = tanhf(acc[i][4] + bias[4]);
            o1.y = tanhf(acc[i][5] + bias[5]);
            o1.z = tanhf(acc[i][6] + bias[6]);
            o1.w = tanhf(acc[i][7] + bias[7]);
            *(float4*)&dst[0] = o0;
            *(float4*)&dst[4] = o1;
        }
    }

    // Copy pool (copy-only CTAs arrive here immediately).
    copy_role((const float4*)memory, (float4*)out, veh_idx, lane);
}

extern "C" void kernel_launch(void* const* d_in, const int* in_sizes, int n_in,
                              void* d_out, int out_size)
{
    const float* memory    = (const float*)d_in[0];
    const int*   veh_idx   = (const int*)d_in[1];
    const float* veh_repr  = (const float*)d_in[2];
    const float* cust_repr = (const float*)d_in[3];
    const float* edge_emb  = (const float*)d_in[4];
    const float* W_in      = (const float*)d_in[5];
    const float* b_in      = (const float*)d_in[6];
    const float* W_h       = (const float*)d_in[7];
    const float* b_h       = (const float*)d_in[8];
    float*       out       = (float*)d_out;

    reset_kernel<<<1, 1>>>();
    fused_kernel<<<TOTAL_CTAS, 256>>>(memory, veh_idx, veh_repr, cust_repr,
                                      edge_emb, W_in, b_in, W_h, b_h, out);
}

// round 5
// speedup vs baseline: 2.6860x; 1.0405x over previous
#include <cuda_runtime.h>
#include <cstdint>

// Problem constants: N=4096, L_V=64, H=512, D=256
constexpr int NB   = 4096;
constexpr int LV   = 64;
constexpr int HD   = 512;
constexpr int DD   = 256;
constexpr int K1   = 3 * DD;   // 768
constexpr int KTOT = K1 + HD;  // 1280

// GEMM tiling
constexpr int BM = 128, BN = 128, BK = 16;
constexpr int TM = 8,   TN = 8;
constexpr int NIT  = KTOT / BK;  // 80
constexpr int ASTR = 16;         // A-row stride (cp.async pattern is conflict-free unpadded)
constexpr int GEMM_CTAS  = (NB / BM) * (HD / BN);  // 128
constexpr int TOTAL_CTAS = 304;                    // 2 per SM on 152 SMs

// Copy pool
constexpr int ROWS_TOTAL = NB * LV;                // 262144 rows of 512 floats
constexpr int NUM_GRABS  = ROWS_TOTAL / 32;        // 8192, 32 rows per grab

__device__ int g_copy_ctr;

__global__ void reset_kernel() { g_copy_ctr = 0; }

// ---------------- PTX helpers ----------------
__device__ __forceinline__ uint32_t s2u(const void* p) {
    uint32_t a;
    asm("{ .reg .u64 t; cvta.to.shared.u64 t, %1; cvt.u32.u64 %0, t; }"
        : "=r"(a) : "l"(p));
    return a;
}
__device__ __forceinline__ void cp16(uint32_t dst, const void* src) {
    asm volatile("cp.async.cg.shared.global [%0], [%1], 16;" :: "r"(dst), "l"(src));
}
__device__ __forceinline__ void cp_commit() {
    asm volatile("cp.async.commit_group;");
}
template <int N>
__device__ __forceinline__ void cp_wait() {
    asm volatile("cp.async.wait_group %0;" :: "n"(N));
}
// packed fp32x2: duplicate scalar into both halves
__device__ __forceinline__ unsigned long long dup2(float v) {
    unsigned long long r;
    asm("mov.b64 %0, {%1, %1};" : "=l"(r) : "f"(v));
    return r;
}
// d = a * b + d on packed fp32 pairs (FFMA2 — full fp32 precision, 2 FMA/instr)
__device__ __forceinline__ void ffma2(unsigned long long& d,
                                      unsigned long long a,
                                      unsigned long long b) {
    asm("fma.rn.f32x2 %0, %1, %2, %0;" : "+l"(d) : "l"(a), "l"(b));
}
__device__ __forceinline__ void unpack2(unsigned long long v, float& lo, float& hi) {
    asm("mov.b64 {%0, %1}, %2;" : "=f"(lo), "=f"(hi) : "l"(v));
}

// --------------------------------------------------------------------------
// Copy role: work-stealing passthrough. Each warp grabs 32 rows; 4 rows per
// group with 16 LDG.128 in flight, stores skip the row the GEMM scatters.
// --------------------------------------------------------------------------
__device__ __forceinline__ void copy_role(const float4* __restrict__ src,
                                          float4* __restrict__ dst,
                                          const int* __restrict__ veh_idx,
                                          int lane)
{
    for (;;) {
        int c;
        if (lane == 0) c = atomicAdd(&g_copy_ctr, 1);
        c = __shfl_sync(0xffffffffu, c, 0);
        if (c >= NUM_GRABS) return;

        const int r0   = c * 32;            // multiple of 32 -> same n whole grab
        const int n    = r0 >> 6;
        const int skip = veh_idx[n] & (LV - 1);
        const int l0   = r0 & 63;           // 0 or 32

        for (int g = 0; g < 8; g++) {       // 8 groups of 4 rows
            float4 v[16];
            size_t base = (size_t)(r0 + g * 4) * (HD / 4) + lane;
            #pragma unroll
            for (int rr = 0; rr < 4; rr++)
                #pragma unroll
                for (int q = 0; q < 4; q++)
                    v[rr * 4 + q] = src[base + rr * 128 + q * 32];
            #pragma unroll
            for (int rr = 0; rr < 4; rr++) {
                if (l0 + g * 4 + rr == skip) continue;   // GEMM owns this row
                #pragma unroll
                for (int q = 0; q < 4; q++)
                    dst[base + rr * 128 + q * 32] = v[rr * 4 + q];
            }
        }
    }
}

// --------------------------------------------------------------------------
// Fused kernel. bids [0,128): one 128x128 tile of
//   tanh(X@W_in + cur_h@W_h + b) scattered into out[n, idx[n], :]
// using a cp.async double-buffered mainloop with FFMA2 (fma.rn.f32x2) math.
// All CTAs end in (copy-only CTAs start in) the copy pool.
// --------------------------------------------------------------------------
__global__ __launch_bounds__(256, 2)
void fused_kernel(const float* __restrict__ memory,
                  const int*   __restrict__ veh_idx,
                  const float* __restrict__ veh_repr,
                  const float* __restrict__ cust_repr,
                  const float* __restrict__ edge_emb,
                  const float* __restrict__ W_in,
                  const float* __restrict__ b_in,
                  const float* __restrict__ W_h,
                  const float* __restrict__ b_h,
                  float* __restrict__ out)
{
    __shared__ float As2[2][BM][ASTR];   // A tiles, [m][k]
    __shared__ float Bs[2][BK][BN];      // B tiles, [k][n]
    __shared__ int   idx_s[BM];

    const int tid  = threadIdx.x;
    const int bid  = blockIdx.x;
    const int lane = tid & 31;

    if (bid < GEMM_CTAS) {
        const int block_m = (bid >> 2) * BM;
        const int block_n = (bid & 3) * BN;

        if (tid < BM) idx_s[tid] = veh_idx[block_m + tid] & (LV - 1);
        __syncthreads();

        // --- A cp.async mapping: 512 16B-chunks = 128 m x 4 k-chunks; 2/thread
        const int m0  = tid >> 2;            // 0..63
        const int kc  = (tid & 3) * 4;       // 0,4,8,12
        const int gm0 = block_m + m0;
        const int gm1 = gm0 + 64;
        const size_t memrow0 = ((size_t)gm0 * LV + idx_s[m0])      * HD;
        const size_t memrow1 = ((size_t)gm1 * LV + idx_s[m0 + 64]) * HD;
        const uint32_t aDst0 = s2u(&As2[0][m0][kc]);
        const uint32_t aDst1 = s2u(&As2[0][m0 + 64][kc]);

        // --- B cp.async mapping: 512 chunks = 16 k x 32 n-chunks; 2/thread
        const int kb = tid >> 5;             // 0..7 (+8 for second)
        const int nc = (tid & 31) * 4;
        const uint32_t bDst0 = s2u(&Bs[0][kb][nc]);
        const uint32_t bDst1 = s2u(&Bs[0][kb + 8][nc]);

        auto issue_tile = [&](int it, int buf) {
            const int k0 = it * BK;
            const uint32_t aoff = buf ? (uint32_t)(BM * ASTR * 4) : 0u;
            const uint32_t boff = buf ? (uint32_t)(BK * BN * 4)   : 0u;
            const float *s0, *s1;
            if (k0 < DD) {
                s0 = veh_repr + (size_t)gm0 * DD + k0 + kc;
                s1 = veh_repr + (size_t)gm1 * DD + k0 + kc;
            } else if (k0 < 2 * DD) {
                const int o = k0 - DD;
                s0 = cust_repr + (size_t)gm0 * DD + o + kc;
                s1 = cust_repr + (size_t)gm1 * DD + o + kc;
            } else if (k0 < K1) {
                const int o = k0 - 2 * DD;
                s0 = edge_emb + (size_t)gm0 * DD + o + kc;
                s1 = edge_emb + (size_t)gm1 * DD + o + kc;
            } else {
                const int o = k0 - K1;
                s0 = memory + memrow0 + o + kc;
                s1 = memory + memrow1 + o + kc;
            }
            cp16(aDst0 + aoff, s0);
            cp16(aDst1 + aoff, s1);

            const int gk0 = k0 + kb;
            const int gk1 = gk0 + 8;
            const float* w0 = (gk0 < K1) ? (W_in + (size_t)gk0 * HD)
                                         : (W_h + (size_t)(gk0 - K1) * HD);
            const float* w1 = (gk1 < K1) ? (W_in + (size_t)gk1 * HD)
                                         : (W_h + (size_t)(gk1 - K1) * HD);
            cp16(bDst0 + boff, w0 + block_n + nc);
            cp16(bDst1 + boff, w1 + block_n + nc);
            cp_commit();
        };

        const int tm = (tid >> 4) * TM;     // (tid/16)*8
        const int tn = (tid & 15) * TN;     // (tid%16)*8

        // packed accumulators: acc[i][j2] holds columns (tn+2j2, tn+2j2+1)
        unsigned long long acc[TM][TN / 2];
        #pragma unroll
        for (int i = 0; i < TM; i++)
            #pragma unroll
            for (int j = 0; j < TN / 2; j++) acc[i][j] = 0ull;

        issue_tile(0, 0);

        for (int it = 0; it < NIT; it++) {
            const int buf = it & 1;
            if (it + 1 < NIT) {
                issue_tile(it + 1, buf ^ 1);
                cp_wait<1>();                // tile 'it' complete
            } else {
                cp_wait<0>();
            }
            __syncthreads();

            #pragma unroll
            for (int k2 = 0; k2 < BK / 2; k2++) {
                float2 a01[TM];
                #pragma unroll
                for (int i = 0; i < TM; i++)
                    a01[i] = *(const float2*)&As2[buf][tm + i][2 * k2];

                // B pairs load directly as packed 64-bit (adjacent n-columns)
                ulonglong2 B00 = *(const ulonglong2*)&Bs[buf][2 * k2][tn];
                ulonglong2 B01 = *(const ulonglong2*)&Bs[buf][2 * k2][tn + 4];
                ulonglong2 B10 = *(const ulonglong2*)&Bs[buf][2 * k2 + 1][tn];
                ulonglong2 B11 = *(const ulonglong2*)&Bs[buf][2 * k2 + 1][tn + 4];
                unsigned long long b0[4] = {B00.x, B00.y, B01.x, B01.y};
                unsigned long long b1[4] = {B10.x, B10.y, B11.x, B11.y};

                #pragma unroll
                for (int i = 0; i < TM; i++) {
                    const unsigned long long a0 = dup2(a01[i].x);
                    const unsigned long long a1 = dup2(a01[i].y);
                    #pragma unroll
                    for (int j = 0; j < 4; j++) {
                        ffma2(acc[i][j], a0, b0[j]);
                        ffma2(acc[i][j], a1, b1[j]);
                    }
                }
            }
            __syncthreads();   // buffer 'buf' free for tile it+2's cp.async
        }

        // ---- epilogue: unpack + bias + tanh, scatter to out[n, idx[n], :] ----
        float bias[TN];
        #pragma unroll
        for (int j = 0; j < TN; j++) {
            const int n = block_n + tn + j;
            bias[j] = b_in[n] + b_h[n];
        }
        #pragma unroll
        for (int i = 0; i < TM; i++) {
            const int gm = block_m + tm + i;
            float* dst = &out[((size_t)gm * LV + idx_s[tm + i]) * HD
                              + block_n + tn];
            float o[TN];
            #pragma unroll
            for (int j = 0; j < 4; j++)
                unpack2(acc[i][j], o[2 * j], o[2 * j + 1]);
            float4 o0, o1;
            o0.x = tanhf(o[0] + bias[0]);
            o0.y = tanhf(o[1] + bias[1]);
            o0.z = tanhf(o[2] + bias[2]);
            o0.w = tanhf(o[3] + bias[3]);
            o1.x = tanhf(o[4] + bias[4]);
            o1.y = tanhf(o[5] + bias[5]);
            o1.z = tanhf(o[6] + bias[6]);
            o1.w = tanhf(o[7] + bias[7]);
            *(float4*)&dst[0] = o0;
            *(float4*)&dst[4] = o1;
        }
    }

    // Copy pool (copy-only CTAs arrive here immediately).
    copy_role((const float4*)memory, (float4*)out, veh_idx, lane);
}

extern "C" void kernel_launch(void* const* d_in, const int* in_sizes, int n_in,
                              void* d_out, int out_size)
{
    const float* memory    = (const float*)d_in[0];
    const int*   veh_idx   = (const int*)d_in[1];
    const float* veh_repr  = (const float*)d_in[2];
    const float* cust_repr = (const float*)d_in[3];
    const float* edge_emb  = (const float*)d_in[4];
    const float* W_in      = (const float*)d_in[5];
    const float* b_in      = (const float*)d_in[6];
    const float* W_h       = (const float*)d_in[7];
    const float* b_h       = (const float*)d_in[8];
    float*       out       = (float*)d_out;

    reset_kernel<<<1, 1>>>();
    fused_kernel<<<TOTAL_CTAS, 256>>>(memory, veh_idx, veh_repr, cust_repr,
                                      edge_emb, W_in, b_in, W_h, b_h, out);
}